// round 14
// baseline (speedup 1.0000x reference)
#include <cuda_runtime.h>
#include <cstdint>

#define BS   8
#define SEQ  1024
#define DIM  1024
#define NH   16
#define HD   64
#define NNB  50

typedef unsigned long long ull;
struct __align__(16) u64x2 { ull a, b; };

__device__ __forceinline__ ull fma2(ull a, ull b, ull c) {
    ull d;
    asm("fma.rn.f32x2 %0, %1, %2, %3;" : "=l"(d) : "l"(a), "l"(b), "l"(c));
    return d;
}
__device__ __forceinline__ ull pack2(float x, float y) {
    ull d;
    asm("mov.b64 %0, {%1, %2};" : "=l"(d) : "f"(x), "f"(y));
    return d;
}
__device__ __forceinline__ float lo32(ull v) { return __uint_as_float((unsigned)(v & 0xffffffffu)); }
__device__ __forceinline__ float hi32(ull v) { return __uint_as_float((unsigned)(v >> 32)); }

__device__ __forceinline__ void cpa4(uint32_t dst, const void* src) {
    asm volatile("cp.async.ca.shared.global [%0], [%1], 4;" :: "r"(dst), "l"(src) : "memory");
}
#define CP_COMMIT()  asm volatile("cp.async.commit_group;" ::: "memory")
#define CP_WAIT(n)   asm volatile("cp.async.wait_group %0;" :: "n"(n) : "memory")

// ---------------- scratch (static device globals; no allocation) ----------------
__device__ __align__(16) float g_xn [BS*DIM];           // pooled neighbors
__device__ __align__(16) float g_q  [BS*DIM];           // query projection (already /8)
__device__ __align__(16) float g_ws [BS*NH*DIM];        // per-head score weight vectors
__device__ __align__(16) float g_scp[16][BS*NH*SEQ];    // partial scores (k-split 16)
__device__ __align__(16) float g_w  [BS*NH*SEQ];        // softmax weights
__device__ __align__(16) float g_xwp[16][BS*NH*DIM];    // partial weighted pools (s-split 16)
__device__ __align__(16) float g_xw [BS*NH*DIM];        // weighted pooled x per head
__device__ __align__(16) float g_ctx[BS*DIM];           // context vector per batch
__device__ __align__(16) float g_out[BS*DIM];           // attention output per batch

// ---------------- K1: masked mean-pool. grid (4 dim-chunks, BS), 128 thr, n-split 2 ----------------
__global__ __launch_bounds__(128) void k_pool(const float* __restrict__ xnb,
                                              const float* __restrict__ nm) {
    int b = blockIdx.y;
    int c = blockIdx.x;
    int iloc = threadIdx.x & 63, nh = threadIdx.x >> 6;
    __shared__ float snm[NNB];
    __shared__ __align__(16) float4 part[64];
    if (threadIdx.x < NNB) snm[threadIdx.x] = nm[b*NNB + threadIdx.x];
    __syncthreads();
    float den = 0.f;
    #pragma unroll
    for (int n = 0; n < NNB; n++) den += snm[n];
    float inv = 1.f / den;
    int i = c*256 + iloc*4;
    float4 a = make_float4(0.f, 0.f, 0.f, 0.f);
    int nbeg = nh*25;
    #pragma unroll 5
    for (int n = nbeg; n < nbeg + 25; n++) {
        float4 v = *(const float4*)&xnb[(b*NNB + n)*DIM + i];
        float w = snm[n];
        a.x += v.x*w; a.y += v.y*w; a.z += v.z*w; a.w += v.w*w;
    }
    if (nh == 1) part[iloc] = a;
    __syncthreads();
    if (nh == 0) {
        float4 p = part[iloc];
        a.x = (a.x + p.x)*inv; a.y = (a.y + p.y)*inv;
        a.z = (a.z + p.z)*inv; a.w = (a.w + p.w)*inv;
        *(float4*)&g_xn[b*DIM + i] = a;
    }
}

// ---------------- K2: q[b,j] = (qw[j,:]·xn[b,:] + qb[j]) / 8 ----------------
__global__ __launch_bounds__(256) void k_q(const float* __restrict__ qw,
                                           const float* __restrict__ qb) {
    int j = blockIdx.x;
    float p[BS];
    #pragma unroll
    for (int b = 0; b < BS; b++) p[b] = 0.f;
    #pragma unroll
    for (int it = 0; it < 4; it++) {
        int i = threadIdx.x + it*256;
        float wv = qw[j*DIM + i];
        #pragma unroll
        for (int b = 0; b < BS; b++) p[b] += wv * g_xn[b*DIM + i];
    }
    #pragma unroll
    for (int off = 16; off; off >>= 1)
        #pragma unroll
        for (int b = 0; b < BS; b++) p[b] += __shfl_down_sync(0xffffffffu, p[b], off);
    __shared__ float red[8][BS];
    int w = threadIdx.x >> 5, lane = threadIdx.x & 31;
    if (lane == 0) {
        #pragma unroll
        for (int b = 0; b < BS; b++) red[w][b] = p[b];
    }
    __syncthreads();
    if (threadIdx.x < BS) {
        int b = threadIdx.x;
        float s = 0.f;
        #pragma unroll
        for (int w2 = 0; w2 < 8; w2++) s += red[w2][b];
        g_q[b*DIM + j] = (s + qb[j]) * 0.125f;
    }
}

// ---------------- K3: ws[b,h,i]. grid (16 ic, 16 h), 128 thr, jj-split 2 ----------------
__global__ __launch_bounds__(128) void k_ws(const float* __restrict__ kw) {
    int ic = blockIdx.x;               // 0..15 -> i-range 64
    int h  = blockIdx.y;
    int iloc = threadIdx.x & 63, jh = threadIdx.x >> 6;
    int i  = ic*64 + iloc;
    __shared__ float qs[BS][HD];
    __shared__ float part[BS][64];
    for (int e = threadIdx.x; e < BS*HD; e += 128) {
        int b = e >> 6, jj = e & 63;
        qs[b][jj] = g_q[b*DIM + h*HD + jj];
    }
    __syncthreads();
    float acc[BS];
    #pragma unroll
    for (int b = 0; b < BS; b++) acc[b] = 0.f;
    int jbeg = jh*32;
    #pragma unroll 4
    for (int jj = jbeg; jj < jbeg + 32; jj++) {
        float kwv = kw[(h*HD + jj)*DIM + i];
        #pragma unroll
        for (int b = 0; b < BS; b++) acc[b] += qs[b][jj] * kwv;
    }
    if (jh == 1) {
        #pragma unroll
        for (int b = 0; b < BS; b++) part[b][iloc] = acc[b];
    }
    __syncthreads();
    if (jh == 0) {
        #pragma unroll
        for (int b = 0; b < BS; b++)
            g_ws[(b*NH + h)*DIM + i] = acc[b] + part[b][iloc];
    }
}

// ---------------- K4: partial scores. grid (16 ksplit, 8 stile, 8 b), 128 thr ----------------
// cp.async double-buffered, conflict-free odd-stride (17) smem layout.
// Lane owns one s-row, accumulates all 16 heads as 8 packed f32x2.
__global__ __launch_bounds__(128) void k_scores(const float* __restrict__ x) {
    int ks = blockIdx.x;           // k range [ks*64, ks*64+64)
    int st = blockIdx.y;           // 128 seq rows
    int b  = blockIdx.z;
    int s0 = st*128, k0 = ks*64;
    __shared__ __align__(16) float xs[2][128*17 + 4];  // row stride 17 (gcd(17,32)=1)
    __shared__ __align__(16) float wss[64*20];         // [kk][16 h + pad4]
    int tid = threadIdx.x;
    int s_loc = tid;               // thread owns one s row (warp lanes consecutive)
    const float* xbase = &x[(b*SEQ + s0)*DIM + k0];
    uint32_t xsb[2];
    xsb[0] = (uint32_t)__cvta_generic_to_shared(&xs[0][0]);
    xsb[1] = (uint32_t)__cvta_generic_to_shared(&xs[1][0]);

#define SC_ISSUE(c) { \
    uint32_t dstb = xsb[(c)&1]; \
    _Pragma("unroll") \
    for (int it = 0; it < 16; it++) { \
        int e = tid + it*128; \
        int kk = e & 15, ss = e >> 4; \
        cpa4(dstb + (uint32_t)(ss*17 + kk)*4u, xbase + ss*DIM + (c)*16 + kk); \
    } \
    CP_COMMIT(); }

    // stage all w (64 kk x 16 h) into registers, then smem
    float wv[8];
    #pragma unroll
    for (int it = 0; it < 8; it++) {
        int e = tid + it*128;
        int kk = e & 63, h = e >> 6;
        wv[it] = g_ws[(b*NH + h)*DIM + k0 + kk];
    }

    SC_ISSUE(0);
    SC_ISSUE(1);

    #pragma unroll
    for (int it = 0; it < 8; it++) {
        int e = tid + it*128;
        int kk = e & 63, h = e >> 6;
        wss[kk*20 + h] = wv[it];
    }
    CP_WAIT(1);        // chunk 0 complete (chunk 1 still pending)
    __syncthreads();   // w + chunk 0 visible to all

    ull acc[8];
    #pragma unroll
    for (int p = 0; p < 8; p++) acc[p] = 0ull;

    #pragma unroll
    for (int c = 0; c < 4; c++) {
        const float* xrow = &xs[c & 1][s_loc*17];
        const float* wp0  = &wss[c*16*20];
        #pragma unroll
        for (int kk = 0; kk < 16; kk++) {
            float xv = xrow[kk];                       // conflict-free (stride 17)
            ull xd = pack2(xv, xv);
            const float* wp = wp0 + kk*20;
            u64x2 w0 = *(const u64x2*)&wp[0];
            u64x2 w1 = *(const u64x2*)&wp[4];
            u64x2 w2 = *(const u64x2*)&wp[8];
            u64x2 w3 = *(const u64x2*)&wp[12];
            acc[0] = fma2(w0.a, xd, acc[0]); acc[1] = fma2(w0.b, xd, acc[1]);
            acc[2] = fma2(w1.a, xd, acc[2]); acc[3] = fma2(w1.b, xd, acc[3]);
            acc[4] = fma2(w2.a, xd, acc[4]); acc[5] = fma2(w2.b, xd, acc[5]);
            acc[6] = fma2(w3.a, xd, acc[6]); acc[7] = fma2(w3.b, xd, acc[7]);
        }
        if (c < 3) {
            __syncthreads();               // buffer c&1 now free
            if (c < 2) {
                SC_ISSUE(c+2);             // refill freed buffer
                CP_WAIT(1);                // chunk c+1 complete (c+2 pending)
            } else {
                CP_WAIT(0);                // last chunk complete
            }
            __syncthreads();               // visible to all warps
        }
    }
#undef SC_ISSUE

    float* dst = g_scp[ks];
    int rbase = b*NH*SEQ + s0 + s_loc;
    #pragma unroll
    for (int p = 0; p < 8; p++) {
        dst[rbase + (2*p  )*SEQ] = lo32(acc[p]);
        dst[rbase + (2*p+1)*SEQ] = hi32(acc[p]);
    }
}

// ---------------- K5: softmax over seq per (b,h); sums the 16 k-split partials ----------------
__global__ __launch_bounds__(256) void k_softmax(const int* __restrict__ mask) {
    int h = blockIdx.x, b = blockIdx.y;
    int base = (b*NH + h)*SEQ;
    int tid = threadIdx.x;
    float v[4];
    float m = -3.4e38f;
    #pragma unroll
    for (int t = 0; t < 4; t++) {
        int s = tid + t*256;
        float sc = 0.f;
        #pragma unroll
        for (int ks = 0; ks < 16; ks++) sc += g_scp[ks][base + s];
        if (mask[b*SEQ + s] == 0) sc = -1e30f;
        v[t] = sc;
        m = fmaxf(m, sc);
    }
    __shared__ float sred[8];
    int w = tid >> 5, lane = tid & 31;
    #pragma unroll
    for (int off = 16; off; off >>= 1) m = fmaxf(m, __shfl_xor_sync(0xffffffffu, m, off));
    if (lane == 0) sred[w] = m;
    __syncthreads();
    float m0 = sred[0];
    #pragma unroll
    for (int w2 = 1; w2 < 8; w2++) m0 = fmaxf(m0, sred[w2]);
    __syncthreads();
    float sum = 0.f;
    #pragma unroll
    for (int t = 0; t < 4; t++) { v[t] = expf(v[t] - m0); sum += v[t]; }
    #pragma unroll
    for (int off = 16; off; off >>= 1) sum += __shfl_xor_sync(0xffffffffu, sum, off);
    if (lane == 0) sred[w] = sum;
    __syncthreads();
    float tot = 0.f;
    #pragma unroll
    for (int w2 = 0; w2 < 8; w2++) tot += sred[w2];
    float inv = 1.f / tot;
    #pragma unroll
    for (int t = 0; t < 4; t++) g_w[base + tid + t*256] = v[t] * inv;
}

// ---------------- K6: partial weighted pools. grid (16 schunk, 4 ichunk, 8 b), f32x2 ----------------
__global__ __launch_bounds__(256) void k_xw(const float* __restrict__ x) {
    int sc = blockIdx.x;   // seq chunk (64)
    int ic = blockIdx.y;   // dim chunk (256)
    int b  = blockIdx.z;
    int i  = ic*256 + threadIdx.x;
    __shared__ __align__(16) float wt[64*20];   // [s][16 h + pad4]
    for (int e = threadIdx.x; e < 1024; e += 256) {
        int s = e & 63, h = e >> 6;
        wt[s*20 + h] = g_w[(b*NH + h)*SEQ + sc*64 + s];
    }
    __syncthreads();
    ull acc[8];
    #pragma unroll
    for (int p = 0; p < 8; p++) acc[p] = 0ull;
    const float* xp = &x[(b*SEQ + sc*64)*DIM + i];
    #pragma unroll 16
    for (int ss = 0; ss < 64; ss++) {
        float xv = xp[ss*DIM];
        ull xd = pack2(xv, xv);
        const float* wr = &wt[ss*20];
        u64x2 w0 = *(const u64x2*)&wr[0];
        u64x2 w1 = *(const u64x2*)&wr[4];
        u64x2 w2 = *(const u64x2*)&wr[8];
        u64x2 w3 = *(const u64x2*)&wr[12];
        acc[0] = fma2(w0.a, xd, acc[0]); acc[1] = fma2(w0.b, xd, acc[1]);
        acc[2] = fma2(w1.a, xd, acc[2]); acc[3] = fma2(w1.b, xd, acc[3]);
        acc[4] = fma2(w2.a, xd, acc[4]); acc[5] = fma2(w2.b, xd, acc[5]);
        acc[6] = fma2(w3.a, xd, acc[6]); acc[7] = fma2(w3.b, xd, acc[7]);
    }
    float* dst = g_xwp[sc];
    #pragma unroll
    for (int p = 0; p < 8; p++) {
        dst[(b*NH + 2*p  )*DIM + i] = lo32(acc[p]);
        dst[(b*NH + 2*p+1)*DIM + i] = hi32(acc[p]);
    }
}

// ---------------- K6b: reduce the 16 seq-chunk partials ----------------
__global__ __launch_bounds__(256) void k_xwred() {
    int idx = blockIdx.x*256 + threadIdx.x;   // 512 blocks -> 131072
    float s = 0.f;
    #pragma unroll
    for (int sc = 0; sc < 16; sc++) s += g_xwp[sc][idx];
    g_xw[idx] = s;
}

// ---------------- K7a: context[b,j] = vw[j,:]·xw[b, j/64, :] + vb[j] ----------------
__global__ __launch_bounds__(256) void k_ctx(const float* __restrict__ vw,
                                             const float* __restrict__ vb) {
    int j = blockIdx.x;
    int h = j >> 6;
    float p[BS];
    #pragma unroll
    for (int b = 0; b < BS; b++) p[b] = 0.f;
    #pragma unroll
    for (int it = 0; it < 4; it++) {
        int i = threadIdx.x + it*256;
        float wv = vw[j*DIM + i];
        #pragma unroll
        for (int b = 0; b < BS; b++) p[b] += wv * g_xw[(b*NH + h)*DIM + i];
    }
    #pragma unroll
    for (int off = 16; off; off >>= 1)
        #pragma unroll
        for (int b = 0; b < BS; b++) p[b] += __shfl_down_sync(0xffffffffu, p[b], off);
    __shared__ float red[8][BS];
    int w = threadIdx.x >> 5, lane = threadIdx.x & 31;
    if (lane == 0) {
        #pragma unroll
        for (int b = 0; b < BS; b++) red[w][b] = p[b];
    }
    __syncthreads();
    if (threadIdx.x < BS) {
        int b = threadIdx.x;
        float s = 0.f;
        #pragma unroll
        for (int w2 = 0; w2 < 8; w2++) s += red[w2][b];
        g_ctx[b*DIM + j] = s + vb[j];
    }
}

// ---------------- K7b: out[b,j] = ow[j,:]·ctx[b,:] + ob[j] ----------------
__global__ __launch_bounds__(256) void k_out(const float* __restrict__ ow,
                                             const float* __restrict__ ob) {
    int j = blockIdx.x;
    float p[BS];
    #pragma unroll
    for (int b = 0; b < BS; b++) p[b] = 0.f;
    #pragma unroll
    for (int it = 0; it < 4; it++) {
        int i = threadIdx.x + it*256;
        float wv = ow[j*DIM + i];
        #pragma unroll
        for (int b = 0; b < BS; b++) p[b] += wv * g_ctx[b*DIM + i];
    }
    #pragma unroll
    for (int off = 16; off; off >>= 1)
        #pragma unroll
        for (int b = 0; b < BS; b++) p[b] += __shfl_down_sync(0xffffffffu, p[b], off);
    __shared__ float red[8][BS];
    int w = threadIdx.x >> 5, lane = threadIdx.x & 31;
    if (lane == 0) {
        #pragma unroll
        for (int b = 0; b < BS; b++) red[w][b] = p[b];
    }
    __syncthreads();
    if (threadIdx.x < BS) {
        int b = threadIdx.x;
        float s = 0.f;
        #pragma unroll
        for (int w2 = 0; w2 < 8; w2++) s += red[w2][b];
        g_out[b*DIM + j] = s + ob[j];
    }
}

// ---------------- K8: y[b,s,:] = LN(x[b,s,:] + out[b,:]) * g + beta ----------------
__global__ __launch_bounds__(256) void k_ln(const float* __restrict__ x,
                                            const float* __restrict__ lg,
                                            const float* __restrict__ lb,
                                            float* __restrict__ y) {
    int row  = blockIdx.x*8 + (threadIdx.x >> 5);   // 8192 rows, warp per row
    int lane = threadIdx.x & 31;
    int b    = row >> 10;
    const float4* X4 = (const float4*)x;
    const float4* O4 = (const float4*)g_out;
    float4 hv[8];
    float sum = 0.f, sq = 0.f;
    #pragma unroll
    for (int j = 0; j < 8; j++) {
        float4 xv = X4[row*256 + lane + j*32];
        float4 ov = O4[b*256  + lane + j*32];
        float4 h;
        h.x = xv.x + ov.x; h.y = xv.y + ov.y; h.z = xv.z + ov.z; h.w = xv.w + ov.w;
        hv[j] = h;
        sum += h.x + h.y + h.z + h.w;
        sq  += h.x*h.x + h.y*h.y + h.z*h.z + h.w*h.w;
    }
    #pragma unroll
    for (int off = 16; off; off >>= 1) {
        sum += __shfl_xor_sync(0xffffffffu, sum, off);
        sq  += __shfl_xor_sync(0xffffffffu, sq,  off);
    }
    float mu  = sum * (1.f/1024.f);
    float var = sq  * (1.f/1024.f) - mu*mu;
    float rs  = rsqrtf(var + 1e-12f);
    const float4* G4 = (const float4*)lg;
    const float4* B4 = (const float4*)lb;
    float4* Y4 = (float4*)y;
    #pragma unroll
    for (int j = 0; j < 8; j++) {
        float4 gv = G4[lane + j*32];
        float4 bv = B4[lane + j*32];
        float4 o;
        o.x = (hv[j].x - mu)*rs*gv.x + bv.x;
        o.y = (hv[j].y - mu)*rs*gv.y + bv.y;
        o.z = (hv[j].z - mu)*rs*gv.z + bv.z;
        o.w = (hv[j].w - mu)*rs*gv.w + bv.w;
        Y4[row*256 + lane + j*32] = o;
    }
}

// ---------------- launch ----------------
extern "C" void kernel_launch(void* const* d_in, const int* in_sizes, int n_in,
                              void* d_out, int out_size) {
    const float* x    = (const float*)d_in[0];
    const float* xnb  = (const float*)d_in[1];
    const int*   mask = (const int*)  d_in[2];
    const float* nm   = (const float*)d_in[3];
    const float* qw   = (const float*)d_in[4];
    const float* qb   = (const float*)d_in[5];
    const float* kw   = (const float*)d_in[6];
    // d_in[7] = kb: cancels in softmax (uniform shift per (b,h) row) -> unused
    const float* vw   = (const float*)d_in[8];
    const float* vb   = (const float*)d_in[9];
    const float* ow   = (const float*)d_in[10];
    const float* ob   = (const float*)d_in[11];
    const float* lg   = (const float*)d_in[12];
    const float* lb   = (const float*)d_in[13];
    float* y = (float*)d_out;

    k_pool   <<<dim3(4, BS), 128>>>(xnb, nm);
    k_q      <<<DIM, 256>>>(qw, qb);
    k_ws     <<<dim3(16, NH), 128>>>(kw);
    k_scores <<<dim3(16, 8, BS), 128>>>(x);
    k_softmax<<<dim3(NH, BS), 256>>>(mask);
    k_xw     <<<dim3(16, 4, BS), 256>>>(x);
    k_xwred  <<<512, 256>>>();
    k_ctx    <<<DIM, 256>>>(vw, vb);
    k_out    <<<DIM, 256>>>(ow, ob);
    k_ln     <<<1024, 256>>>(x, lg, lb, y);
}

// round 15
// speedup vs baseline: 1.0320x; 1.0320x over previous
#include <cuda_runtime.h>
#include <cstdint>

#define BS   8
#define SEQ  1024
#define DIM  1024
#define NH   16
#define HD   64
#define NNB  50

typedef unsigned long long ull;
struct __align__(16) u64x2 { ull a, b; };

__device__ __forceinline__ ull fma2(ull a, ull b, ull c) {
    ull d;
    asm("fma.rn.f32x2 %0, %1, %2, %3;" : "=l"(d) : "l"(a), "l"(b), "l"(c));
    return d;
}
__device__ __forceinline__ ull pack2(float x, float y) {
    ull d;
    asm("mov.b64 %0, {%1, %2};" : "=l"(d) : "f"(x), "f"(y));
    return d;
}
__device__ __forceinline__ float lo32(ull v) { return __uint_as_float((unsigned)(v & 0xffffffffu)); }
__device__ __forceinline__ float hi32(ull v) { return __uint_as_float((unsigned)(v >> 32)); }

// ---------------- scratch (static device globals; no allocation) ----------------
__device__ __align__(16) float g_xn [BS*DIM];           // pooled neighbors
__device__ __align__(16) float g_q  [BS*DIM];           // query projection (already /8)
__device__ __align__(16) float g_ws [BS*NH*DIM];        // per-head score weight vectors
__device__ __align__(16) float g_scp[16][BS*NH*SEQ];    // partial scores (k-split 16)
__device__ __align__(16) float g_w  [BS*NH*SEQ];        // softmax weights
__device__ __align__(16) float g_xwp[16][BS*NH*DIM];    // partial weighted pools (s-split 16)
__device__ __align__(16) float g_xw [BS*NH*DIM];        // weighted pooled x per head
__device__ __align__(16) float g_ctx[BS*DIM];           // context vector per batch
__device__ __align__(16) float g_out[BS*DIM];           // attention output per batch

// ---------------- K1: masked mean-pool. grid (4 dim-chunks, BS), 128 thr, n-split 2 ----------------
__global__ __launch_bounds__(128) void k_pool(const float* __restrict__ xnb,
                                              const float* __restrict__ nm) {
    int b = blockIdx.y;
    int c = blockIdx.x;
    int iloc = threadIdx.x & 63, nh = threadIdx.x >> 6;
    __shared__ float snm[NNB];
    __shared__ __align__(16) float4 part[64];
    if (threadIdx.x < NNB) snm[threadIdx.x] = nm[b*NNB + threadIdx.x];
    __syncthreads();
    float den = 0.f;
    #pragma unroll
    for (int n = 0; n < NNB; n++) den += snm[n];
    float inv = 1.f / den;
    int i = c*256 + iloc*4;
    float4 a = make_float4(0.f, 0.f, 0.f, 0.f);
    int nbeg = nh*25;
    #pragma unroll 5
    for (int n = nbeg; n < nbeg + 25; n++) {
        float4 v = *(const float4*)&xnb[(b*NNB + n)*DIM + i];
        float w = snm[n];
        a.x += v.x*w; a.y += v.y*w; a.z += v.z*w; a.w += v.w*w;
    }
    if (nh == 1) part[iloc] = a;
    __syncthreads();
    if (nh == 0) {
        float4 p = part[iloc];
        a.x = (a.x + p.x)*inv; a.y = (a.y + p.y)*inv;
        a.z = (a.z + p.z)*inv; a.w = (a.w + p.w)*inv;
        *(float4*)&g_xn[b*DIM + i] = a;
    }
}

// ---------------- K2: q[b,j] = (qw[j,:]·xn[b,:] + qb[j]) / 8 ----------------
__global__ __launch_bounds__(256) void k_q(const float* __restrict__ qw,
                                           const float* __restrict__ qb) {
    int j = blockIdx.x;
    float p[BS];
    #pragma unroll
    for (int b = 0; b < BS; b++) p[b] = 0.f;
    #pragma unroll
    for (int it = 0; it < 4; it++) {
        int i = threadIdx.x + it*256;
        float wv = qw[j*DIM + i];
        #pragma unroll
        for (int b = 0; b < BS; b++) p[b] += wv * g_xn[b*DIM + i];
    }
    #pragma unroll
    for (int off = 16; off; off >>= 1)
        #pragma unroll
        for (int b = 0; b < BS; b++) p[b] += __shfl_down_sync(0xffffffffu, p[b], off);
    __shared__ float red[8][BS];
    int w = threadIdx.x >> 5, lane = threadIdx.x & 31;
    if (lane == 0) {
        #pragma unroll
        for (int b = 0; b < BS; b++) red[w][b] = p[b];
    }
    __syncthreads();
    if (threadIdx.x < BS) {
        int b = threadIdx.x;
        float s = 0.f;
        #pragma unroll
        for (int w2 = 0; w2 < 8; w2++) s += red[w2][b];
        g_q[b*DIM + j] = (s + qb[j]) * 0.125f;
    }
}

// ---------------- K3: ws[b,h,i]. grid (16 ic, 16 h), 128 thr, jj-split 2 ----------------
__global__ __launch_bounds__(128) void k_ws(const float* __restrict__ kw) {
    int ic = blockIdx.x;               // 0..15 -> i-range 64
    int h  = blockIdx.y;
    int iloc = threadIdx.x & 63, jh = threadIdx.x >> 6;
    int i  = ic*64 + iloc;
    __shared__ float qs[BS][HD];
    __shared__ float part[BS][64];
    for (int e = threadIdx.x; e < BS*HD; e += 128) {
        int b = e >> 6, jj = e & 63;
        qs[b][jj] = g_q[b*DIM + h*HD + jj];
    }
    __syncthreads();
    float acc[BS];
    #pragma unroll
    for (int b = 0; b < BS; b++) acc[b] = 0.f;
    int jbeg = jh*32;
    #pragma unroll 4
    for (int jj = jbeg; jj < jbeg + 32; jj++) {
        float kwv = kw[(h*HD + jj)*DIM + i];
        #pragma unroll
        for (int b = 0; b < BS; b++) acc[b] += qs[b][jj] * kwv;
    }
    if (jh == 1) {
        #pragma unroll
        for (int b = 0; b < BS; b++) part[b][iloc] = acc[b];
    }
    __syncthreads();
    if (jh == 0) {
        #pragma unroll
        for (int b = 0; b < BS; b++)
            g_ws[(b*NH + h)*DIM + i] = acc[b] + part[b][iloc];
    }
}

// ---------------- K4: partial scores. grid (16 ksplit, 4 stile, 8 b), 128 thr ----------------
// 8h x 4s per-thread tile: per kk = 3 LDS.128 feeding 16 FFMA2 (2x arithmetic
// intensity per smem op vs R7). Staging layout identical to proven R5/R7.
__global__ __launch_bounds__(128) void k_scores(const float* __restrict__ x) {
    int ks = blockIdx.x;           // k range [ks*64, ks*64+64)
    int st = blockIdx.y;           // 256 seq rows
    int b  = blockIdx.z;
    int s0 = st*256, k0 = ks*64;
    __shared__ __align__(16) float xs [16*260];   // [kk][256 s + pad4]
    __shared__ __align__(16) float wss[16*20];    // [kk][16 h + pad4]
    int tid = threadIdx.x;
    int wid = tid >> 5, lane = tid & 31;
    int sh = wid & 1;              // s-half (0/1)
    int hb = (wid >> 1) * 8;       // head base (0/8)
    int scol = sh*128 + lane*4;    // col base in xs row

    ull acc[8][2];
    #pragma unroll
    for (int h = 0; h < 8; h++) { acc[h][0] = 0ull; acc[h][1] = 0ull; }

    #pragma unroll
    for (int kc = 0; kc < 4; kc++) {
        int kb = k0 + kc*16;
        #pragma unroll
        for (int it = 0; it < 8; it++) {
            int e = tid + it*128;          // 0..1023
            int kk4 = e & 3, ss = e >> 2;  // float4 along k, ss 0..255
            float4 v = *(const float4*)&x[(b*SEQ + s0 + ss)*DIM + kb + kk4*4];
            xs[(kk4*4+0)*260 + ss] = v.x;
            xs[(kk4*4+1)*260 + ss] = v.y;
            xs[(kk4*4+2)*260 + ss] = v.z;
            xs[(kk4*4+3)*260 + ss] = v.w;
        }
        #pragma unroll
        for (int it = 0; it < 2; it++) {
            int e = tid + it*128;
            int kk = e & 15, h = e >> 4;
            wss[kk*20 + h] = g_ws[(b*NH + h)*DIM + kb + kk];
        }
        __syncthreads();
        #pragma unroll
        for (int kk = 0; kk < 16; kk++) {
            u64x2 xp = *(const u64x2*)&xs[kk*260 + scol];   // (s0,s1),(s2,s3)
            float4 wa = *(const float4*)&wss[kk*20 + hb];      // heads hb..hb+3
            float4 wb = *(const float4*)&wss[kk*20 + hb + 4];  // heads hb+4..hb+7
            ull w0 = pack2(wa.x, wa.x);
            ull w1 = pack2(wa.y, wa.y);
            ull w2 = pack2(wa.z, wa.z);
            ull w3 = pack2(wa.w, wa.w);
            ull w4 = pack2(wb.x, wb.x);
            ull w5 = pack2(wb.y, wb.y);
            ull w6 = pack2(wb.z, wb.z);
            ull w7 = pack2(wb.w, wb.w);
            acc[0][0] = fma2(w0, xp.a, acc[0][0]); acc[0][1] = fma2(w0, xp.b, acc[0][1]);
            acc[1][0] = fma2(w1, xp.a, acc[1][0]); acc[1][1] = fma2(w1, xp.b, acc[1][1]);
            acc[2][0] = fma2(w2, xp.a, acc[2][0]); acc[2][1] = fma2(w2, xp.b, acc[2][1]);
            acc[3][0] = fma2(w3, xp.a, acc[3][0]); acc[3][1] = fma2(w3, xp.b, acc[3][1]);
            acc[4][0] = fma2(w4, xp.a, acc[4][0]); acc[4][1] = fma2(w4, xp.b, acc[4][1]);
            acc[5][0] = fma2(w5, xp.a, acc[5][0]); acc[5][1] = fma2(w5, xp.b, acc[5][1]);
            acc[6][0] = fma2(w6, xp.a, acc[6][0]); acc[6][1] = fma2(w6, xp.b, acc[6][1]);
            acc[7][0] = fma2(w7, xp.a, acc[7][0]); acc[7][1] = fma2(w7, xp.b, acc[7][1]);
        }
        __syncthreads();
    }

    float* dst = g_scp[ks];
    #pragma unroll
    for (int h = 0; h < 8; h++) {
        int r = (b*NH + hb + h)*SEQ + s0 + scol;
        *(float4*)&dst[r] = make_float4(lo32(acc[h][0]), hi32(acc[h][0]),
                                        lo32(acc[h][1]), hi32(acc[h][1]));
    }
}

// ---------------- K5: softmax over seq per (b,h); sums the 16 k-split partials ----------------
__global__ __launch_bounds__(256) void k_softmax(const int* __restrict__ mask) {
    int h = blockIdx.x, b = blockIdx.y;
    int base = (b*NH + h)*SEQ;
    int tid = threadIdx.x;
    float v[4];
    float m = -3.4e38f;
    #pragma unroll
    for (int t = 0; t < 4; t++) {
        int s = tid + t*256;
        float sc = 0.f;
        #pragma unroll
        for (int ks = 0; ks < 16; ks++) sc += g_scp[ks][base + s];
        if (mask[b*SEQ + s] == 0) sc = -1e30f;
        v[t] = sc;
        m = fmaxf(m, sc);
    }
    __shared__ float sred[8];
    int w = tid >> 5, lane = tid & 31;
    #pragma unroll
    for (int off = 16; off; off >>= 1) m = fmaxf(m, __shfl_xor_sync(0xffffffffu, m, off));
    if (lane == 0) sred[w] = m;
    __syncthreads();
    float m0 = sred[0];
    #pragma unroll
    for (int w2 = 1; w2 < 8; w2++) m0 = fmaxf(m0, sred[w2]);
    __syncthreads();
    float sum = 0.f;
    #pragma unroll
    for (int t = 0; t < 4; t++) { v[t] = expf(v[t] - m0); sum += v[t]; }
    #pragma unroll
    for (int off = 16; off; off >>= 1) sum += __shfl_xor_sync(0xffffffffu, sum, off);
    if (lane == 0) sred[w] = sum;
    __syncthreads();
    float tot = 0.f;
    #pragma unroll
    for (int w2 = 0; w2 < 8; w2++) tot += sred[w2];
    float inv = 1.f / tot;
    #pragma unroll
    for (int t = 0; t < 4; t++) g_w[base + tid + t*256] = v[t] * inv;
}

// ---------------- K6: partial weighted pools. grid (16 schunk, 4 ichunk, 8 b), f32x2 ----------------
__global__ __launch_bounds__(256) void k_xw(const float* __restrict__ x) {
    int sc = blockIdx.x;   // seq chunk (64)
    int ic = blockIdx.y;   // dim chunk (256)
    int b  = blockIdx.z;
    int i  = ic*256 + threadIdx.x;
    __shared__ __align__(16) float wt[64*20];   // [s][16 h + pad4]
    for (int e = threadIdx.x; e < 1024; e += 256) {
        int s = e & 63, h = e >> 6;
        wt[s*20 + h] = g_w[(b*NH + h)*SEQ + sc*64 + s];
    }
    __syncthreads();
    ull acc[8];
    #pragma unroll
    for (int p = 0; p < 8; p++) acc[p] = 0ull;
    const float* xp = &x[(b*SEQ + sc*64)*DIM + i];
    #pragma unroll 16
    for (int ss = 0; ss < 64; ss++) {
        float xv = xp[ss*DIM];
        ull xd = pack2(xv, xv);
        const float* wr = &wt[ss*20];
        u64x2 w0 = *(const u64x2*)&wr[0];
        u64x2 w1 = *(const u64x2*)&wr[4];
        u64x2 w2 = *(const u64x2*)&wr[8];
        u64x2 w3 = *(const u64x2*)&wr[12];
        acc[0] = fma2(w0.a, xd, acc[0]); acc[1] = fma2(w0.b, xd, acc[1]);
        acc[2] = fma2(w1.a, xd, acc[2]); acc[3] = fma2(w1.b, xd, acc[3]);
        acc[4] = fma2(w2.a, xd, acc[4]); acc[5] = fma2(w2.b, xd, acc[5]);
        acc[6] = fma2(w3.a, xd, acc[6]); acc[7] = fma2(w3.b, xd, acc[7]);
    }
    float* dst = g_xwp[sc];
    #pragma unroll
    for (int p = 0; p < 8; p++) {
        dst[(b*NH + 2*p  )*DIM + i] = lo32(acc[p]);
        dst[(b*NH + 2*p+1)*DIM + i] = hi32(acc[p]);
    }
}

// ---------------- K6b: reduce the 16 seq-chunk partials ----------------
__global__ __launch_bounds__(256) void k_xwred() {
    int idx = blockIdx.x*256 + threadIdx.x;   // 512 blocks -> 131072
    float s = 0.f;
    #pragma unroll
    for (int sc = 0; sc < 16; sc++) s += g_xwp[sc][idx];
    g_xw[idx] = s;
}

// ---------------- K7a: context[b,j] = vw[j,:]·xw[b, j/64, :] + vb[j] ----------------
__global__ __launch_bounds__(256) void k_ctx(const float* __restrict__ vw,
                                             const float* __restrict__ vb) {
    int j = blockIdx.x;
    int h = j >> 6;
    float p[BS];
    #pragma unroll
    for (int b = 0; b < BS; b++) p[b] = 0.f;
    #pragma unroll
    for (int it = 0; it < 4; it++) {
        int i = threadIdx.x + it*256;
        float wv = vw[j*DIM + i];
        #pragma unroll
        for (int b = 0; b < BS; b++) p[b] += wv * g_xw[(b*NH + h)*DIM + i];
    }
    #pragma unroll
    for (int off = 16; off; off >>= 1)
        #pragma unroll
        for (int b = 0; b < BS; b++) p[b] += __shfl_down_sync(0xffffffffu, p[b], off);
    __shared__ float red[8][BS];
    int w = threadIdx.x >> 5, lane = threadIdx.x & 31;
    if (lane == 0) {
        #pragma unroll
        for (int b = 0; b < BS; b++) red[w][b] = p[b];
    }
    __syncthreads();
    if (threadIdx.x < BS) {
        int b = threadIdx.x;
        float s = 0.f;
        #pragma unroll
        for (int w2 = 0; w2 < 8; w2++) s += red[w2][b];
        g_ctx[b*DIM + j] = s + vb[j];
    }
}

// ---------------- K7b: out[b,j] = ow[j,:]·ctx[b,:] + ob[j] ----------------
__global__ __launch_bounds__(256) void k_out(const float* __restrict__ ow,
                                             const float* __restrict__ ob) {
    int j = blockIdx.x;
    float p[BS];
    #pragma unroll
    for (int b = 0; b < BS; b++) p[b] = 0.f;
    #pragma unroll
    for (int it = 0; it < 4; it++) {
        int i = threadIdx.x + it*256;
        float wv = ow[j*DIM + i];
        #pragma unroll
        for (int b = 0; b < BS; b++) p[b] += wv * g_ctx[b*DIM + i];
    }
    #pragma unroll
    for (int off = 16; off; off >>= 1)
        #pragma unroll
        for (int b = 0; b < BS; b++) p[b] += __shfl_down_sync(0xffffffffu, p[b], off);
    __shared__ float red[8][BS];
    int w = threadIdx.x >> 5, lane = threadIdx.x & 31;
    if (lane == 0) {
        #pragma unroll
        for (int b = 0; b < BS; b++) red[w][b] = p[b];
    }
    __syncthreads();
    if (threadIdx.x < BS) {
        int b = threadIdx.x;
        float s = 0.f;
        #pragma unroll
        for (int w2 = 0; w2 < 8; w2++) s += red[w2][b];
        g_out[b*DIM + j] = s + ob[j];
    }
}

// ---------------- K8: y[b,s,:] = LN(x[b,s,:] + out[b,:]) * g + beta ----------------
__global__ __launch_bounds__(256) void k_ln(const float* __restrict__ x,
                                            const float* __restrict__ lg,
                                            const float* __restrict__ lb,
                                            float* __restrict__ y) {
    int row  = blockIdx.x*8 + (threadIdx.x >> 5);   // 8192 rows, warp per row
    int lane = threadIdx.x & 31;
    int b    = row >> 10;
    const float4* X4 = (const float4*)x;
    const float4* O4 = (const float4*)g_out;
    float4 hv[8];
    float sum = 0.f, sq = 0.f;
    #pragma unroll
    for (int j = 0; j < 8; j++) {
        float4 xv = X4[row*256 + lane + j*32];
        float4 ov = O4[b*256  + lane + j*32];
        float4 h;
        h.x = xv.x + ov.x; h.y = xv.y + ov.y; h.z = xv.z + ov.z; h.w = xv.w + ov.w;
        hv[j] = h;
        sum += h.x + h.y + h.z + h.w;
        sq  += h.x*h.x + h.y*h.y + h.z*h.z + h.w*h.w;
    }
    #pragma unroll
    for (int off = 16; off; off >>= 1) {
        sum += __shfl_xor_sync(0xffffffffu, sum, off);
        sq  += __shfl_xor_sync(0xffffffffu, sq,  off);
    }
    float mu  = sum * (1.f/1024.f);
    float var = sq  * (1.f/1024.f) - mu*mu;
    float rs  = rsqrtf(var + 1e-12f);
    const float4* G4 = (const float4*)lg;
    const float4* B4 = (const float4*)lb;
    float4* Y4 = (float4*)y;
    #pragma unroll
    for (int j = 0; j < 8; j++) {
        float4 gv = G4[lane + j*32];
        float4 bv = B4[lane + j*32];
        float4 o;
        o.x = (hv[j].x - mu)*rs*gv.x + bv.x;
        o.y = (hv[j].y - mu)*rs*gv.y + bv.y;
        o.z = (hv[j].z - mu)*rs*gv.z + bv.z;
        o.w = (hv[j].w - mu)*rs*gv.w + bv.w;
        Y4[row*256 + lane + j*32] = o;
    }
}

// ---------------- launch ----------------
extern "C" void kernel_launch(void* const* d_in, const int* in_sizes, int n_in,
                              void* d_out, int out_size) {
    const float* x    = (const float*)d_in[0];
    const float* xnb  = (const float*)d_in[1];
    const int*   mask = (const int*)  d_in[2];
    const float* nm   = (const float*)d_in[3];
    const float* qw   = (const float*)d_in[4];
    const float* qb   = (const float*)d_in[5];
    const float* kw   = (const float*)d_in[6];
    // d_in[7] = kb: cancels in softmax (uniform shift per (b,h) row) -> unused
    const float* vw   = (const float*)d_in[8];
    const float* vb   = (const float*)d_in[9];
    const float* ow   = (const float*)d_in[10];
    const float* ob   = (const float*)d_in[11];
    const float* lg   = (const float*)d_in[12];
    const float* lb   = (const float*)d_in[13];
    float* y = (float*)d_out;

    k_pool   <<<dim3(4, BS), 128>>>(xnb, nm);
    k_q      <<<DIM, 256>>>(qw, qb);
    k_ws     <<<dim3(16, NH), 128>>>(kw);
    k_scores <<<dim3(16, 4, BS), 128>>>(x);
    k_softmax<<<dim3(NH, BS), 256>>>(mask);
    k_xw     <<<dim3(16, 4, BS), 256>>>(x);
    k_xwred  <<<512, 256>>>();
    k_ctx    <<<DIM, 256>>>(vw, vb);
    k_out    <<<DIM, 256>>>(ow, ob);
    k_ln     <<<1024, 256>>>(x, lg, lb, y);
}